// round 1
// baseline (speedup 1.0000x reference)
#include <cuda_runtime.h>
#include <cuda_bf16.h>

// ROI mean-pool via per-(b,c)-plane integral image in shared memory.
// fmap:  [B=64, C=256, H=80, W=80] float32
// boxes: [B=64, N=100, 4] xyxy in [0,640]
// out:   [B, N, C] float32
//
// One CTA per (b,c) plane. Load plane (25.6 KB, contiguous) -> SMEM,
// build padded 81x81 inclusive 2D prefix sum (row 0 / col 0 are zero border),
// then each box = 4 SMEM reads + inclusion-exclusion.

#define Bn   64
#define Cn   256
#define Hn   80
#define Wn   80
#define Nn   100
#define SSTR 81   // odd stride -> conflict-free column-wise access

__global__ __launch_bounds__(256, 1)
void roi_integral_pool_kernel(const float* __restrict__ fmap,
                              const float* __restrict__ boxes,
                              float* __restrict__ out)
{
    __shared__ float S[(Hn + 1) * SSTR];   // 81*81 floats = 26,244 B

    const int p   = blockIdx.x;            // plane id = b*Cn + c
    const int b   = p >> 8;                // / 256
    const int c   = p & 255;               // % 256
    const int tid = threadIdx.x;

    const float* __restrict__ plane = fmap + (size_t)p * (Hn * Wn);

    // Zero borders: row 0 (81 entries) and column 0 of rows 1..80.
    if (tid < SSTR)                 S[tid] = 0.0f;
    if (tid >= 128 && tid < 208)    S[(tid - 127) * SSTR] = 0.0f;

    // Coalesced float4 load of the plane into the interior S[r+1][x+1..x+4].
    // 80*80/4 = 1600 float4 elements; 20 float4 per row.
    for (int i = tid; i < (Hn * Wn) / 4; i += 256) {
        float4 v = reinterpret_cast<const float4*>(plane)[i];
        int r  = i / (Wn / 4);
        int c4 = i % (Wn / 4);
        float* dst = &S[(r + 1) * SSTR + c4 * 4 + 1];
        dst[0] = v.x; dst[1] = v.y; dst[2] = v.z; dst[3] = v.w;
    }
    __syncthreads();

    // Row-wise inclusive scan: one thread per row (80 threads).
    // Consecutive threads hit addresses stride-81 apart -> 81%32=17 (odd), no conflicts.
    if (tid < Hn) {
        float* row = &S[(tid + 1) * SSTR];
        float carry = 0.0f;
        #pragma unroll 8
        for (int x = 1; x <= Wn; ++x) {
            carry += row[x];
            row[x] = carry;
        }
    }
    __syncthreads();

    // Column-wise inclusive scan: one thread per column (80 threads).
    // Consecutive threads hit consecutive addresses per iteration -> no conflicts.
    if (tid < Wn) {
        const int x = tid + 1;
        float carry = 0.0f;
        #pragma unroll 8
        for (int y = 1; y <= Hn; ++y) {
            float v = S[y * SSTR + x];
            carry += v;
            S[y * SSTR + x] = carry;
        }
    }
    __syncthreads();

    // Box evaluation: threads 0..99 each handle one box.
    const float* __restrict__ bx = boxes + (size_t)b * (Nn * 4);
    float* __restrict__ ob = out + (size_t)b * (Nn * Cn) + c;

    for (int n = tid; n < Nn; n += 256) {
        float4 bb = reinterpret_cast<const float4*>(bx)[n];
        // Match JAX exactly: IEEE div by 640, IEEE mul by 80, trunc-to-int, clip.
        int x1 = min(max((int)(__fmul_rn(__fdiv_rn(bb.x, 640.0f), 80.0f)), 0), Wn);
        int y1 = min(max((int)(__fmul_rn(__fdiv_rn(bb.y, 640.0f), 80.0f)), 0), Hn);
        int x2 = min(max((int)(__fmul_rn(__fdiv_rn(bb.z, 640.0f), 80.0f)), 0), Wn);
        int y2 = min(max((int)(__fmul_rn(__fdiv_rn(bb.w, 640.0f), 80.0f)), 0), Hn);

        float s = S[y2 * SSTR + x2] - S[y1 * SSTR + x2]
                - S[y2 * SSTR + x1] + S[y1 * SSTR + x1];

        int dy = y2 - y1;
        int dx = x2 - x1;
        bool valid = (dy > 0) && (dx > 0);
        int  area  = max(dy * dx, 1);

        ob[(size_t)n * Cn] = valid ? s / (float)area : 0.0f;
    }
}

extern "C" void kernel_launch(void* const* d_in, const int* in_sizes, int n_in,
                              void* d_out, int out_size)
{
    const float* fmap  = (const float*)d_in[0];   // [64,256,80,80]
    const float* boxes = (const float*)d_in[1];   // [64,100,4]
    float*       out   = (float*)d_out;           // [64,100,256]

    (void)in_sizes; (void)n_in; (void)out_size;

    roi_integral_pool_kernel<<<Bn * Cn, 256>>>(fmap, boxes, out);
}